// round 10
// baseline (speedup 1.0000x reference)
#include <cuda_runtime.h>
#include <cuda_fp16.h>
#include <cstdint>

// OuterProductMean — fp16 mma.m16n8k16, fused, 2 CTAs/SM, 1024 thr.
//
//  ln_wo  : blocks 0..255: LayerNorm + dual proj -> g_ah[s][m], g_bh[s][n] (fp16)
//           blocks 256..287: g_wo16 = fp16(wo)
//  fused  : per CTA (4 i x 8 j = 32 pairs), 32 warps:
//    phase1: o[128 (i,c)][256 (j,d)] = sum_s a*b  (mma fp16, K=128 in 2 halves)
//    stage o -> Os[p=32][k2=1024] fp16 (swizzled, conflict-free)
//    phase2: Z[32][128 z] = Os * wo^T (K=1024, 16 cp.async chunks of 64,
//            4-way k-split + SMEM reduction)

#define S_DIM 128
#define R_DIM 256
#define CM    256
#define CC    32
#define CZ    128
#define MDIM  (R_DIM * CC)          // 8192

__device__ __half g_ah[(size_t)S_DIM * MDIM];   // 2 MB [s][m]
__device__ __half g_bh[(size_t)S_DIM * MDIM];   // 2 MB [s][n]
__device__ __half g_wo16[(size_t)CZ * CC * CC]; // 256 KB [z][k2]

// ---------------------------------------------------------------- helpers
__device__ __forceinline__ uint32_t su32(const void* p) {
    uint32_t a;
    asm("{ .reg .u64 t; cvta.to.shared.u64 t, %1; cvt.u32.u64 %0, t; }"
        : "=r"(a) : "l"(p));
    return a;
}
__device__ __forceinline__ void cp16(void* dst_smem, const void* src) {
    asm volatile("cp.async.cg.shared.global [%0], [%1], 16;"
                 :: "r"(su32(dst_smem)), "l"(src));
}
__device__ __forceinline__ void cp_commit() {
    asm volatile("cp.async.commit_group;" ::: "memory");
}
template <int N>
__device__ __forceinline__ void cp_wait() {
    asm volatile("cp.async.wait_group %0;" :: "n"(N) : "memory");
}

// D(16x8,f32) += A(16x16,f16 row) * B(16x8,f16 col)
__device__ __forceinline__ void mma16(float* d, const uint32_t* a, uint32_t b0, uint32_t b1) {
    asm volatile(
        "mma.sync.aligned.m16n8k16.row.col.f32.f16.f16.f32 "
        "{%0,%1,%2,%3}, {%4,%5,%6,%7}, {%8,%9}, {%0,%1,%2,%3};"
        : "+f"(d[0]), "+f"(d[1]), "+f"(d[2]), "+f"(d[3])
        : "r"(a[0]), "r"(a[1]), "r"(a[2]), "r"(a[3]), "r"(b0), "r"(b1));
}

__device__ __forceinline__ uint32_t h2bits(__half2 h) {
    return *reinterpret_cast<uint32_t*>(&h);
}

// ---------------------------------------------------------------- ln + proj (+ wo convert)
#define LN_STRIDE 264
#define LN_SMEM ((64 + 32) * LN_STRIDE * 4)

__global__ __launch_bounds__(256, 1)
void ln_wo_kernel(const float* __restrict__ m,
                  const float* __restrict__ ln_w, const float* __restrict__ ln_b,
                  const float* __restrict__ w1, const float* __restrict__ b1,
                  const float* __restrict__ w2, const float* __restrict__ b2,
                  const float* __restrict__ wo) {
    if (blockIdx.x >= 2 * S_DIM) {           // wo -> fp16 (32 blocks)
        const int base = ((blockIdx.x - 2 * S_DIM) * 256 + threadIdx.x) * 16;
        #pragma unroll
        for (int t = 0; t < 4; t++) {
            const float4 v = *(const float4*)&wo[base + 4 * t];
            uint2 u;
            u.x = h2bits(__floats2half2_rn(v.x, v.y));
            u.y = h2bits(__floats2half2_rn(v.z, v.w));
            *(uint2*)&g_wo16[base + 4 * t] = u;
        }
        return;
    }

    extern __shared__ __align__(16) float sm_[];
    float* ws = sm_;                     // [64][264]
    float* xs = sm_ + 64 * LN_STRIDE;    // [32][264]

    const int s = blockIdx.x >> 1;
    const int half = blockIdx.x & 1;
    const int tid = threadIdx.x, w = tid >> 5, lane = tid & 31;

    for (int idx = tid; idx < 64 * 64; idx += 256) {
        const int row = idx >> 6, k4 = idx & 63;
        const float* src = (row < 32) ? (w1 + (size_t)row * CM)
                                      : (w2 + (size_t)(row - 32) * CM);
        *(float4*)(ws + row * LN_STRIDE + k4 * 4) = *(const float4*)(src + k4 * 4);
    }

    const float4 lw0 = ((const float4*)ln_w)[lane], lw1 = ((const float4*)ln_w)[lane + 32];
    const float4 lb0 = ((const float4*)ln_b)[lane], lb1 = ((const float4*)ln_b)[lane + 32];

    const int o0 = (tid >> 3) * 2, r0 = tid & 7;
    const float bias0 = (o0 < 32) ? b1[o0] : b2[o0 - 32];
    const float bias1 = (o0 < 32) ? b1[o0 + 1] : b2[o0 + 1 - 32];

    for (int b0r = half * 128; b0r < half * 128 + 128; b0r += 32) {
        __syncthreads();
        #pragma unroll
        for (int p = 0; p < 4; p++) {
            const int r = p * 8 + w;
            const float* rowp = m + ((size_t)s * R_DIM + (b0r + r)) * CM;
            const float4 v0 = ((const float4*)rowp)[lane];
            const float4 v1 = ((const float4*)rowp)[lane + 32];
            float sum = v0.x + v0.y + v0.z + v0.w + v1.x + v1.y + v1.z + v1.w;
            #pragma unroll
            for (int o = 16; o; o >>= 1) sum += __shfl_xor_sync(~0u, sum, o);
            const float mu = sum * (1.0f / CM);
            const float d0 = v0.x - mu, d1 = v0.y - mu, d2 = v0.z - mu, d3 = v0.w - mu;
            const float d4 = v1.x - mu, d5 = v1.y - mu, d6 = v1.z - mu, d7 = v1.w - mu;
            float vs = d0*d0 + d1*d1 + d2*d2 + d3*d3 + d4*d4 + d5*d5 + d6*d6 + d7*d7;
            #pragma unroll
            for (int o = 16; o; o >>= 1) vs += __shfl_xor_sync(~0u, vs, o);
            const float rstd = rsqrtf(vs * (1.0f / CM) + 1e-5f);
            float4 y0, y1;
            y0.x = d0 * rstd * lw0.x + lb0.x;  y0.y = d1 * rstd * lw0.y + lb0.y;
            y0.z = d2 * rstd * lw0.z + lb0.z;  y0.w = d3 * rstd * lw0.w + lb0.w;
            y1.x = d4 * rstd * lw1.x + lb1.x;  y1.y = d5 * rstd * lw1.y + lb1.y;
            y1.z = d6 * rstd * lw1.z + lb1.z;  y1.w = d7 * rstd * lw1.w + lb1.w;
            *(float4*)(xs + r * LN_STRIDE + 4 * lane)       = y0;
            *(float4*)(xs + r * LN_STRIDE + 128 + 4 * lane) = y1;
        }
        __syncthreads();

        float acc0[4] = {0.f, 0.f, 0.f, 0.f}, acc1[4] = {0.f, 0.f, 0.f, 0.f};
        const float* wr0 = ws + o0 * LN_STRIDE;
        const float* wr1 = wr0 + LN_STRIDE;
        #pragma unroll 8
        for (int k4 = 0; k4 < 64; k4++) {
            const float4 wa = *(const float4*)(wr0 + k4 * 4);
            const float4 wb = *(const float4*)(wr1 + k4 * 4);
            #pragma unroll
            for (int u = 0; u < 4; u++) {
                const float4 x = *(const float4*)(xs + (r0 + 8 * u) * LN_STRIDE + k4 * 4);
                acc0[u] = fmaf(wa.x, x.x, acc0[u]); acc0[u] = fmaf(wa.y, x.y, acc0[u]);
                acc0[u] = fmaf(wa.z, x.z, acc0[u]); acc0[u] = fmaf(wa.w, x.w, acc0[u]);
                acc1[u] = fmaf(wb.x, x.x, acc1[u]); acc1[u] = fmaf(wb.y, x.y, acc1[u]);
                acc1[u] = fmaf(wb.z, x.z, acc1[u]); acc1[u] = fmaf(wb.w, x.w, acc1[u]);
            }
        }
        #pragma unroll
        for (int u = 0; u < 4; u++) {
            const int i_abs = b0r + r0 + 8 * u;
            const __half2 v = __floats2half2_rn(acc0[u] + bias0, acc1[u] + bias1);
            if (o0 < 32)
                *(__half2*)&g_ah[(size_t)s * MDIM + i_abs * CC + o0] = v;
            else
                *(__half2*)&g_bh[(size_t)s * MDIM + i_abs * CC + (o0 - 32)] = v;
        }
    }
}

// ---------------------------------------------------------------- fused
// SMEM (u32/h2 units), total 25728 u32 = 102912 B -> 2 CTAs/SM:
//   phase1 (per K-half 64): sAh[128 m][36] @0 (4608), sBh[256 n][36] @4608 (9216)
//   Os [32 p][516] @0 (16512)  — reuses phase1 region, swizzled cols
//   wo bufs 2 x [128 z][36] @16512 (2x4608)
//   reduction scratch (10240 fl) reuses region 0 after Os is dead.
#define OPS_STRIDE 36
#define SBH_OFF    (128 * OPS_STRIDE)      // 4608
#define OS_STRIDE  516
#define WO_OFF     16512
#define WO_BUF     (128 * OPS_STRIDE)      // 4608
#define FUSED_SMEM ((WO_OFF + 2 * WO_BUF) * 4)   // 102912 B

// Os column swizzle: value (channel c 0..31, d2 0..15) stored at
//   p*516 + 16*c + ((d2 + 4*((c>>1)&3)) & 15)
// -> Os stores AND phase-2 A-fragment reads are bank-conflict-free.

__device__ __forceinline__ void issue_wo(uint32_t* buf, int cc, int tid) {
    // chunk cc: g_wo16[z][cc*64 .. +63], 128 z x 128 B = 1024 cp16 (1/thread)
    const int z = tid >> 3, q = tid & 7;
    cp16(buf + z * OPS_STRIDE + 4 * q,
         g_wo16 + (size_t)z * 1024 + cc * 64 + 8 * q);
}

__global__ __launch_bounds__(1024, 2)
void fused_kernel(const float* __restrict__ bo, float* __restrict__ out) {
    extern __shared__ __align__(16) uint32_t smu[];
    const int tid = threadIdx.x, w = tid >> 5, lane = tid & 31;
    const int g = lane >> 2, tg = lane & 3;
    const int i0 = blockIdx.x * 4, j0 = blockIdx.y * 8;
    const int m0 = i0 * CC, n0 = j0 * CC;

    uint32_t* wob0 = smu + WO_OFF;
    uint32_t* wob1 = smu + WO_OFF + WO_BUF;
    issue_wo(wob0, 0, tid); cp_commit();
    issue_wo(wob1, 1, tid); cp_commit();

    // ---- phase 1: o[128][256] = A * B^T over k=128 in 2 halves ----
    const int mr = w & 3, nc = w >> 2;          // warp: rows 32*mr, cols 32*nc
    float acc[2][4][4];
    #pragma unroll
    for (int mt = 0; mt < 2; mt++)
        #pragma unroll
        for (int nt = 0; nt < 4; nt++)
            #pragma unroll
            for (int q = 0; q < 4; q++) acc[mt][nt][q] = 0.f;

    #pragma unroll
    for (int kh = 0; kh < 2; kh++) {
        if (kh) __syncthreads();                // prev compute done before reload
        // repack A: 128 m x 32 sp (1 task/thread: 4 m x 1 sp)
        {
            const int sp = tid & 31, mq = tid >> 5;
            const int s0 = kh * 64 + 2 * sp;
            const uint2 r0 = *(const uint2*)&g_ah[(size_t)s0 * MDIM + m0 + 4 * mq];
            const uint2 r1 = *(const uint2*)&g_ah[(size_t)(s0 + 1) * MDIM + m0 + 4 * mq];
            const __half* h0 = (const __half*)&r0;
            const __half* h1 = (const __half*)&r1;
            #pragma unroll
            for (int t = 0; t < 4; t++)
                smu[(4 * mq + t) * OPS_STRIDE + sp] = h2bits(__halves2half2(h0[t], h1[t]));
        }
        // repack B: 256 n x 32 sp (2 tasks/thread)
        #pragma unroll
        for (int it = 0; it < 2; it++) {
            const int idx = it * 1024 + tid;
            const int sp = idx & 31, nq = idx >> 5;
            const int s0 = kh * 64 + 2 * sp;
            const uint2 r0 = *(const uint2*)&g_bh[(size_t)s0 * MDIM + n0 + 4 * nq];
            const uint2 r1 = *(const uint2*)&g_bh[(size_t)(s0 + 1) * MDIM + n0 + 4 * nq];
            const __half* h0 = (const __half*)&r0;
            const __half* h1 = (const __half*)&r1;
            #pragma unroll
            for (int t = 0; t < 4; t++)
                smu[SBH_OFF + (4 * nq + t) * OPS_STRIDE + sp] = h2bits(__halves2half2(h0[t], h1[t]));
        }
        __syncthreads();

        #pragma unroll
        for (int ks = 0; ks < 4; ks++) {
            uint32_t a[2][4];
            #pragma unroll
            for (int mt = 0; mt < 2; mt++) {
                const uint32_t* base = smu + (32 * mr + 16 * mt + g) * OPS_STRIDE + 8 * ks + tg;
                a[mt][0] = base[0];
                a[mt][1] = base[8 * OPS_STRIDE];
                a[mt][2] = base[4];
                a[mt][3] = base[8 * OPS_STRIDE + 4];
            }
            #pragma unroll
            for (int nt = 0; nt < 4; nt++) {
                const uint32_t* bb = smu + SBH_OFF + (32 * nc + 8 * nt + g) * OPS_STRIDE + 8 * ks + tg;
                const uint32_t b0 = bb[0], b1 = bb[4];
                mma16(acc[0][nt], a[0], b0, b1);
                mma16(acc[1][nt], a[1], b0, b1);
            }
        }
    }
    __syncthreads();   // operands dead; region 0 becomes Os

    // ---- stage o -> Os[p][k2] fp16, swizzled (conflict-free) ----
    const int p1 = 8 * mr + nc;                 // this warp's pair (one per warp)
    #pragma unroll
    for (int mt = 0; mt < 2; mt++) {
        #pragma unroll
        for (int nt = 0; nt < 4; nt++) {
            const int d2 = 4 * nt + tg;          // (d>>1), d = 8*nt + 2*tg
            #pragma unroll
            for (int rr = 0; rr < 2; rr++) {
                const int c = 16 * mt + 8 * rr + g;
                const int sw = (d2 + 4 * ((c >> 1) & 3)) & 15;
                smu[p1 * OS_STRIDE + 16 * c + sw] =
                    h2bits(__floats2half2_rn(acc[mt][nt][2 * rr], acc[mt][nt][2 * rr + 1]));
            }
        }
    }

    // ---- phase 2: Z[32][128] = Os * wo^T, 16 chunks of 64 k2 ----
    const int kg = w >> 3, zg = w & 7;          // 4 k-groups x 8 z-groups(16 z)
    float zacc[2][2][4];
    #pragma unroll
    for (int mt = 0; mt < 2; mt++)
        #pragma unroll
        for (int nt = 0; nt < 2; nt++)
            #pragma unroll
            for (int q = 0; q < 4; q++) zacc[mt][nt][q] = 0.f;

    for (int cc = 0; cc < 16; cc++) {
        cp_wait<1>();
        __syncthreads();                        // chunk cc ready; Os visible (cc=0)
        const uint32_t* W = (cc & 1) ? wob1 : wob0;
        const int kb = cc * 32 + kg * 8;        // h2 col base for this warp's k16
        const int q0 = kb + tg;
        const int c_ = q0 >> 4;                 // constant across warp
        const int sw0 = ((q0 & 15)     + 4 * ((c_ >> 1) & 3)) & 15;
        const int sw1 = ((q0 & 15) + 4 + 4 * ((c_ >> 1) & 3)) & 15;
        const int a_off0 = 16 * c_ + sw0, a_off1 = 16 * c_ + sw1;
        uint32_t a[2][4];
        #pragma unroll
        for (int mt = 0; mt < 2; mt++) {
            const uint32_t* base = smu + (16 * mt + g) * OS_STRIDE;
            a[mt][0] = base[a_off0];
            a[mt][1] = base[8 * OS_STRIDE + a_off0];
            a[mt][2] = base[a_off1];
            a[mt][3] = base[8 * OS_STRIDE + a_off1];
        }
        #pragma unroll
        for (int nt = 0; nt < 2; nt++) {
            const uint32_t* bb = W + (16 * zg + 8 * nt + g) * OPS_STRIDE + kg * 8 + tg;
            const uint32_t b0 = bb[0], b1 = bb[4];
            mma16(zacc[0][nt], a[0], b0, b1);
            mma16(zacc[1][nt], a[1], b0, b1);
        }
        __syncthreads();                        // all warps done with this buffer
        if (cc + 2 < 16) issue_wo((cc & 1) ? wob1 : wob0, cc + 2, tid);
        cp_commit();
    }

    // ---- 4-way k reduction via SMEM (Os dead after loop's final barrier) ----
    float* zf = &zacc[0][0][0];                 // 16 floats
    float* scr = (float*)smu;                   // region 0, stride-20 slots
    const int slot = (zg * 32 + lane) * 20;
    if (kg >= 2) {
        float* dst = scr + (kg - 2) * 5120 + slot;
        #pragma unroll
        for (int x = 0; x < 4; x++) *(float4*)&dst[4 * x] = *(float4*)&zf[4 * x];
    }
    __syncthreads();
    if (kg < 2) {
        const float* src = scr + kg * 5120 + slot;
        #pragma unroll
        for (int x = 0; x < 16; x++) zf[x] += src[x];
    }
    __syncthreads();
    if (kg == 1) {
        float* dst = scr + slot;
        #pragma unroll
        for (int x = 0; x < 4; x++) *(float4*)&dst[4 * x] = *(float4*)&zf[4 * x];
    }
    __syncthreads();
    if (kg == 0) {
        const float* src = scr + slot;
        #pragma unroll
        for (int x = 0; x < 16; x++) zf[x] += src[x];

        // ---- epilogue ----
        #pragma unroll
        for (int mt = 0; mt < 2; mt++) {
            #pragma unroll
            for (int nt = 0; nt < 2; nt++) {
                const int zz = 16 * zg + 8 * nt + 2 * tg;
                const float2 bo2 = *(const float2*)&bo[zz];
                #pragma unroll
                for (int rr = 0; rr < 2; rr++) {
                    const int p = 16 * mt + 8 * rr + g;
                    const int i = i0 + (p >> 3), j = j0 + (p & 7);
                    float2 v;
                    v.x = (zacc[mt][nt][2 * rr + 0] + bo2.x) * (1.0f / S_DIM);
                    v.y = (zacc[mt][nt][2 * rr + 1] + bo2.y) * (1.0f / S_DIM);
                    *(float2*)&out[((size_t)i * R_DIM + j) * CZ + zz] = v;
                }
            }
        }
    }
}

// ---------------------------------------------------------------- launch
extern "C" void kernel_launch(void* const* d_in, const int* in_sizes, int n_in,
                              void* d_out, int out_size) {
    const float* m    = (const float*)d_in[0];
    const float* ln_w = (const float*)d_in[1];
    const float* ln_b = (const float*)d_in[2];
    const float* w1   = (const float*)d_in[3];
    const float* b1   = (const float*)d_in[4];
    const float* w2   = (const float*)d_in[5];
    const float* b2   = (const float*)d_in[6];
    const float* wo   = (const float*)d_in[7];
    const float* bo   = (const float*)d_in[8];
    float* out = (float*)d_out;

    cudaFuncSetAttribute(ln_wo_kernel, cudaFuncAttributeMaxDynamicSharedMemorySize, LN_SMEM);
    cudaFuncSetAttribute(fused_kernel, cudaFuncAttributeMaxDynamicSharedMemorySize, FUSED_SMEM);

    ln_wo_kernel<<<2 * S_DIM + 32, 256, LN_SMEM>>>(m, ln_w, ln_b, w1, b1, w2, b2, wo);
    fused_kernel<<<dim3(R_DIM / 4, R_DIM / 8), 1024, FUSED_SMEM>>>(bo, out);
}

// round 13
// speedup vs baseline: 2.2755x; 2.2755x over previous
#include <cuda_runtime.h>
#include <cuda_fp16.h>
#include <cstdint>

// OuterProductMean — fp16 mma.m16n8k16, split GEMMs, 2 CTAs/SM each.
//
//  ln_wo  : blocks 0..255: LayerNorm + dual proj -> g_ah[s][m], g_bh[s][n] (fp16)
//           blocks 256..287: g_wo16 = fp16(wo)
//  per j-chunk (2 chunks of 128 j):
//   gemm1 : o[(i,jl) row][(c,d) k2] fp16 -> g_o32 (64 MB, L2-resident)
//           CTA = 4i x 8j, 128x256x128, 2 n-passes (acc 32 -> 64-reg fit)
//   gemm2 : Z[row][z] = o * wo^T   (M-tile 128, N=128, K=1024 in 16 chunks)

#define S_DIM 128
#define R_DIM 256
#define CM    256
#define CC    32
#define CZ    128
#define MDIM  (R_DIM * CC)          // 8192

__device__ __half   g_ah[(size_t)S_DIM * MDIM];    // 2 MB [s][m]
__device__ __half   g_bh[(size_t)S_DIM * MDIM];    // 2 MB [s][n]
__device__ __half   g_wo16[(size_t)CZ * CC * CC];  // 256 KB [z][k2]
__device__ uint32_t g_o32[(size_t)32768 * 512];    // 64 MB o chunk [row][k2/2]

// ---------------------------------------------------------------- helpers
__device__ __forceinline__ uint32_t su32(const void* p) {
    uint32_t a;
    asm("{ .reg .u64 t; cvta.to.shared.u64 t, %1; cvt.u32.u64 %0, t; }"
        : "=r"(a) : "l"(p));
    return a;
}
__device__ __forceinline__ void cp16(void* dst_smem, const void* src) {
    asm volatile("cp.async.cg.shared.global [%0], [%1], 16;"
                 :: "r"(su32(dst_smem)), "l"(src));
}
__device__ __forceinline__ void cp_commit() {
    asm volatile("cp.async.commit_group;" ::: "memory");
}
template <int N>
__device__ __forceinline__ void cp_wait() {
    asm volatile("cp.async.wait_group %0;" :: "n"(N) : "memory");
}
__device__ __forceinline__ void mma16(float* d, const uint32_t* a, uint32_t b0, uint32_t b1) {
    asm volatile(
        "mma.sync.aligned.m16n8k16.row.col.f32.f16.f16.f32 "
        "{%0,%1,%2,%3}, {%4,%5,%6,%7}, {%8,%9}, {%0,%1,%2,%3};"
        : "+f"(d[0]), "+f"(d[1]), "+f"(d[2]), "+f"(d[3])
        : "r"(a[0]), "r"(a[1]), "r"(a[2]), "r"(a[3]), "r"(b0), "r"(b1));
}
__device__ __forceinline__ uint32_t h2bits(__half2 h) {
    return *reinterpret_cast<uint32_t*>(&h);
}

// ---------------------------------------------------------------- ln + proj (+ wo convert)
#define LN_STRIDE 264
#define LN_SMEM ((64 + 32) * LN_STRIDE * 4)

__global__ __launch_bounds__(256, 1)
void ln_wo_kernel(const float* __restrict__ m,
                  const float* __restrict__ ln_w, const float* __restrict__ ln_b,
                  const float* __restrict__ w1, const float* __restrict__ b1,
                  const float* __restrict__ w2, const float* __restrict__ b2,
                  const float* __restrict__ wo) {
    if (blockIdx.x >= 2 * S_DIM) {           // wo -> fp16 (32 blocks)
        const int base = ((blockIdx.x - 2 * S_DIM) * 256 + threadIdx.x) * 16;
        #pragma unroll
        for (int t = 0; t < 4; t++) {
            const float4 v = *(const float4*)&wo[base + 4 * t];
            uint2 u;
            u.x = h2bits(__floats2half2_rn(v.x, v.y));
            u.y = h2bits(__floats2half2_rn(v.z, v.w));
            *(uint2*)&g_wo16[base + 4 * t] = u;
        }
        return;
    }

    extern __shared__ __align__(16) float sm_[];
    float* ws = sm_;                     // [64][264]
    float* xs = sm_ + 64 * LN_STRIDE;    // [32][264]

    const int s = blockIdx.x >> 1;
    const int half = blockIdx.x & 1;
    const int tid = threadIdx.x, w = tid >> 5, lane = tid & 31;

    for (int idx = tid; idx < 64 * 64; idx += 256) {
        const int row = idx >> 6, k4 = idx & 63;
        const float* src = (row < 32) ? (w1 + (size_t)row * CM)
                                      : (w2 + (size_t)(row - 32) * CM);
        *(float4*)(ws + row * LN_STRIDE + k4 * 4) = *(const float4*)(src + k4 * 4);
    }

    const float4 lw0 = ((const float4*)ln_w)[lane], lw1 = ((const float4*)ln_w)[lane + 32];
    const float4 lb0 = ((const float4*)ln_b)[lane], lb1 = ((const float4*)ln_b)[lane + 32];

    const int o0 = (tid >> 3) * 2, r0 = tid & 7;
    const float bias0 = (o0 < 32) ? b1[o0] : b2[o0 - 32];
    const float bias1 = (o0 < 32) ? b1[o0 + 1] : b2[o0 + 1 - 32];

    for (int b0r = half * 128; b0r < half * 128 + 128; b0r += 32) {
        __syncthreads();
        #pragma unroll
        for (int p = 0; p < 4; p++) {
            const int r = p * 8 + w;
            const float* rowp = m + ((size_t)s * R_DIM + (b0r + r)) * CM;
            const float4 v0 = ((const float4*)rowp)[lane];
            const float4 v1 = ((const float4*)rowp)[lane + 32];
            float sum = v0.x + v0.y + v0.z + v0.w + v1.x + v1.y + v1.z + v1.w;
            #pragma unroll
            for (int o = 16; o; o >>= 1) sum += __shfl_xor_sync(~0u, sum, o);
            const float mu = sum * (1.0f / CM);
            const float d0 = v0.x - mu, d1 = v0.y - mu, d2 = v0.z - mu, d3 = v0.w - mu;
            const float d4 = v1.x - mu, d5 = v1.y - mu, d6 = v1.z - mu, d7 = v1.w - mu;
            float vs = d0*d0 + d1*d1 + d2*d2 + d3*d3 + d4*d4 + d5*d5 + d6*d6 + d7*d7;
            #pragma unroll
            for (int o = 16; o; o >>= 1) vs += __shfl_xor_sync(~0u, vs, o);
            const float rstd = rsqrtf(vs * (1.0f / CM) + 1e-5f);
            float4 y0, y1;
            y0.x = d0 * rstd * lw0.x + lb0.x;  y0.y = d1 * rstd * lw0.y + lb0.y;
            y0.z = d2 * rstd * lw0.z + lb0.z;  y0.w = d3 * rstd * lw0.w + lb0.w;
            y1.x = d4 * rstd * lw1.x + lb1.x;  y1.y = d5 * rstd * lw1.y + lb1.y;
            y1.z = d6 * rstd * lw1.z + lb1.z;  y1.w = d7 * rstd * lw1.w + lb1.w;
            *(float4*)(xs + r * LN_STRIDE + 4 * lane)       = y0;
            *(float4*)(xs + r * LN_STRIDE + 128 + 4 * lane) = y1;
        }
        __syncthreads();

        float acc0[4] = {0.f, 0.f, 0.f, 0.f}, acc1[4] = {0.f, 0.f, 0.f, 0.f};
        const float* wr0 = ws + o0 * LN_STRIDE;
        const float* wr1 = wr0 + LN_STRIDE;
        #pragma unroll 8
        for (int k4 = 0; k4 < 64; k4++) {
            const float4 wa = *(const float4*)(wr0 + k4 * 4);
            const float4 wb = *(const float4*)(wr1 + k4 * 4);
            #pragma unroll
            for (int u = 0; u < 4; u++) {
                const float4 x = *(const float4*)(xs + (r0 + 8 * u) * LN_STRIDE + k4 * 4);
                acc0[u] = fmaf(wa.x, x.x, acc0[u]); acc0[u] = fmaf(wa.y, x.y, acc0[u]);
                acc0[u] = fmaf(wa.z, x.z, acc0[u]); acc0[u] = fmaf(wa.w, x.w, acc0[u]);
                acc1[u] = fmaf(wb.x, x.x, acc1[u]); acc1[u] = fmaf(wb.y, x.y, acc1[u]);
                acc1[u] = fmaf(wb.z, x.z, acc1[u]); acc1[u] = fmaf(wb.w, x.w, acc1[u]);
            }
        }
        #pragma unroll
        for (int u = 0; u < 4; u++) {
            const int i_abs = b0r + r0 + 8 * u;
            const __half2 v = __floats2half2_rn(acc0[u] + bias0, acc1[u] + bias1);
            if (o0 < 32)
                *(__half2*)&g_ah[(size_t)s * MDIM + i_abs * CC + o0] = v;
            else
                *(__half2*)&g_bh[(size_t)s * MDIM + i_abs * CC + (o0 - 32)] = v;
        }
    }
}

// ---------------------------------------------------------------- gemm1
// CTA: 128 (i,c) x 256 (j,d), K=128 resident; 16 warps, 2 n-passes (acc 32).
// SMEM: sAh[128][68] + sBh[256][68] = 26112 u32 = 104448 B -> 2 CTAs/SM.
#define G1_STRIDE 68
#define G1_B_OFF  (128 * G1_STRIDE)
#define G1_SMEM   ((128 * G1_STRIDE + 256 * G1_STRIDE) * 4)

__global__ __launch_bounds__(512, 2)
void gemm1_kernel(int jch) {
    extern __shared__ __align__(16) uint32_t smu[];
    const int tid = threadIdx.x, w = tid >> 5, lane = tid & 31;
    const int g = lane >> 3 ? (lane >> 2) : (lane >> 2), tg = lane & 3;   // g = lane>>2
    const int gq = lane >> 2;
    const int i0 = blockIdx.x * 4;            // i block (0..63)
    const int jb = blockIdx.y * 8;            // local j base (0..120)
    const int m0 = i0 * CC;
    const int n0 = (jch * 128 + jb) * CC;

    // repack A: [s][m] -> smu[m][k] (k-paired h2), 128 m x 64 sp
    #pragma unroll
    for (int it = 0; it < 4; it++) {
        const int idx = it * 512 + tid;
        const int sp = idx & 63, mq = idx >> 6;
        const uint2 r0 = *(const uint2*)&g_ah[(size_t)(2 * sp) * MDIM + m0 + 4 * mq];
        const uint2 r1 = *(const uint2*)&g_ah[(size_t)(2 * sp + 1) * MDIM + m0 + 4 * mq];
        const __half* h0 = (const __half*)&r0;
        const __half* h1 = (const __half*)&r1;
        #pragma unroll
        for (int t = 0; t < 4; t++)
            smu[(4 * mq + t) * G1_STRIDE + sp] = h2bits(__halves2half2(h0[t], h1[t]));
    }
    // repack B: 256 n x 64 sp
    #pragma unroll
    for (int it = 0; it < 8; it++) {
        const int idx = it * 512 + tid;
        const int sp = idx & 63, nq = idx >> 6;
        const uint2 r0 = *(const uint2*)&g_bh[(size_t)(2 * sp) * MDIM + n0 + 4 * nq];
        const uint2 r1 = *(const uint2*)&g_bh[(size_t)(2 * sp + 1) * MDIM + n0 + 4 * nq];
        const __half* h0 = (const __half*)&r0;
        const __half* h1 = (const __half*)&r1;
        #pragma unroll
        for (int t = 0; t < 4; t++)
            smu[G1_B_OFF + (4 * nq + t) * G1_STRIDE + sp] = h2bits(__halves2half2(h0[t], h1[t]));
    }
    __syncthreads();

    const int mr = w & 3, nc = w >> 2;        // 4 m-rows x 4 n-cols warp grid
    #pragma unroll
    for (int np = 0; np < 2; np++) {
        float acc[2][4][4];
        #pragma unroll
        for (int mt = 0; mt < 2; mt++)
            #pragma unroll
            for (int nt = 0; nt < 4; nt++)
                #pragma unroll
                for (int q = 0; q < 4; q++) acc[mt][nt][q] = 0.f;

        #pragma unroll
        for (int ks = 0; ks < 8; ks++) {
            uint32_t a[2][4];
            #pragma unroll
            for (int mt = 0; mt < 2; mt++) {
                const uint32_t* base = smu + (32 * mr + 16 * mt + gq) * G1_STRIDE + 8 * ks + tg;
                a[mt][0] = base[0];
                a[mt][1] = base[8 * G1_STRIDE];
                a[mt][2] = base[4];
                a[mt][3] = base[8 * G1_STRIDE + 4];
            }
            #pragma unroll
            for (int nt = 0; nt < 4; nt++) {
                const uint32_t* bb = smu + G1_B_OFF +
                    (np * 128 + 32 * nc + 8 * nt + gq) * G1_STRIDE + 8 * ks + tg;
                const uint32_t b0 = bb[0], b1 = bb[4];
                mma16(acc[0][nt], a[0], b0, b1);
                mma16(acc[1][nt], a[1], b0, b1);
            }
        }

        // store o: row = (i0+mr)*128 + jb + 4*np + nc ; u32 col = c*16 + 4*nt + tg
        const size_t row = (size_t)(i0 + mr) * 128 + jb + 4 * np + nc;
        uint32_t* orow = g_o32 + row * 512;
        #pragma unroll
        for (int mt = 0; mt < 2; mt++)
            #pragma unroll
            for (int nt = 0; nt < 4; nt++)
                #pragma unroll
                for (int rr = 0; rr < 2; rr++) {
                    const int c = 16 * mt + 8 * rr + gq;
                    orow[c * 16 + 4 * nt + tg] =
                        h2bits(__floats2half2_rn(acc[mt][nt][2 * rr], acc[mt][nt][2 * rr + 1]));
                }
    }
}

// ---------------------------------------------------------------- gemm2
// Z[128 rows][128 z] = O[128][1024] * wo^T; K in 16 chunks of 64 k2, dbl-buf.
// SMEM: 2 x O[128][36] + 2 x W[128][36] = 18432 u32 = 73728 B -> 2 CTAs/SM.
#define G2_STRIDE 36
#define G2_BUF    (128 * G2_STRIDE)               // 4608
#define G2_WOFF   (2 * G2_BUF)                    // 9216
#define G2_SMEM   ((4 * G2_BUF) * 4)              // 73728 B

__device__ __forceinline__ void g2_issue(uint32_t* smu, int buf, int cc, int m0, int tid) {
    uint32_t* ob = smu + buf * G2_BUF;
    uint32_t* wb = smu + G2_WOFF + buf * G2_BUF;
    const uint32_t* wo32 = (const uint32_t*)g_wo16;
    #pragma unroll
    for (int t = 0; t < 2; t++) {
        const int idx = tid + t * 512;
        const int r = idx >> 3, q = idx & 7;
        cp16(ob + r * G2_STRIDE + 4 * q, g_o32 + (size_t)(m0 + r) * 512 + cc * 32 + 4 * q);
        cp16(wb + r * G2_STRIDE + 4 * q, wo32 + (size_t)r * 512 + cc * 32 + 4 * q);
    }
}

__global__ __launch_bounds__(512, 2)
void gemm2_kernel(const float* __restrict__ bo, float* __restrict__ out, int jch) {
    extern __shared__ __align__(16) uint32_t smu[];
    const int tid = threadIdx.x, w = tid >> 5, lane = tid & 31;
    const int gq = lane >> 2, tg = lane & 3;
    const int m0 = blockIdx.x * 128;

    g2_issue(smu, 0, 0, m0, tid); cp_commit();
    g2_issue(smu, 1, 1, m0, tid); cp_commit();

    const int mr = w & 3, nc = w >> 2;
    float acc[2][4][4];
    #pragma unroll
    for (int mt = 0; mt < 2; mt++)
        #pragma unroll
        for (int nt = 0; nt < 4; nt++)
            #pragma unroll
            for (int q = 0; q < 4; q++) acc[mt][nt][q] = 0.f;

    for (int cc = 0; cc < 16; cc++) {
        cp_wait<1>();
        __syncthreads();
        const uint32_t* O = smu + (cc & 1) * G2_BUF;
        const uint32_t* W = smu + G2_WOFF + (cc & 1) * G2_BUF;
        #pragma unroll
        for (int ks = 0; ks < 4; ks++) {
            uint32_t a[2][4];
            #pragma unroll
            for (int mt = 0; mt < 2; mt++) {
                const uint32_t* base = O + (32 * mr + 16 * mt + gq) * G2_STRIDE + 8 * ks + tg;
                a[mt][0] = base[0];
                a[mt][1] = base[8 * G2_STRIDE];
                a[mt][2] = base[4];
                a[mt][3] = base[8 * G2_STRIDE + 4];
            }
            #pragma unroll
            for (int nt = 0; nt < 4; nt++) {
                const uint32_t* bb = W + (32 * nc + 8 * nt + gq) * G2_STRIDE + 8 * ks + tg;
                const uint32_t b0 = bb[0], b1 = bb[4];
                mma16(acc[0][nt], a[0], b0, b1);
                mma16(acc[1][nt], a[1], b0, b1);
            }
        }
        __syncthreads();
        if (cc + 2 < 16) g2_issue(smu, cc & 1, cc + 2, m0, tid);
        cp_commit();
    }

    // epilogue: row -> (i, j); z = 32*nc + 8*nt + 2*tg
    #pragma unroll
    for (int mt = 0; mt < 2; mt++) {
        #pragma unroll
        for (int nt = 0; nt < 4; nt++) {
            const int zz = 32 * nc + 8 * nt + 2 * tg;
            const float2 bo2 = *(const float2*)&bo[zz];
            #pragma unroll
            for (int rr = 0; rr < 2; rr++) {
                const int row = m0 + 32 * mr + 16 * mt + 8 * rr + gq;
                const int i = row >> 7, jl = row & 127;
                const int j = jch * 128 + jl;
                float2 v;
                v.x = (acc[mt][nt][2 * rr + 0] + bo2.x) * (1.0f / S_DIM);
                v.y = (acc[mt][nt][2 * rr + 1] + bo2.y) * (1.0f / S_DIM);
                *(float2*)&out[((size_t)i * R_DIM + j) * CZ + zz] = v;
            }
        }
    }
}

// ---------------------------------------------------------------- launch
extern "C" void kernel_launch(void* const* d_in, const int* in_sizes, int n_in,
                              void* d_out, int out_size) {
    const float* m    = (const float*)d_in[0];
    const float* ln_w = (const float*)d_in[1];
    const float* ln_b = (const float*)d_in[2];
    const float* w1   = (const float*)d_in[3];
    const float* b1   = (const float*)d_in[4];
    const float* w2   = (const float*)d_in[5];
    const float* b2   = (const float*)d_in[6];
    const float* wo   = (const float*)d_in[7];
    const float* bo   = (const float*)d_in[8];
    float* out = (float*)d_out;

    cudaFuncSetAttribute(ln_wo_kernel, cudaFuncAttributeMaxDynamicSharedMemorySize, LN_SMEM);
    cudaFuncSetAttribute(gemm1_kernel, cudaFuncAttributeMaxDynamicSharedMemorySize, G1_SMEM);
    cudaFuncSetAttribute(gemm2_kernel, cudaFuncAttributeMaxDynamicSharedMemorySize, G2_SMEM);

    ln_wo_kernel<<<2 * S_DIM + 32, 256, LN_SMEM>>>(m, ln_w, ln_b, w1, b1, w2, b2, wo);
    for (int jch = 0; jch < 2; jch++) {
        gemm1_kernel<<<dim3(64, 16), 512, G1_SMEM>>>(jch);
        gemm2_kernel<<<256, 512, G2_SMEM>>>(bo, out, jch);
    }
}

// round 15
// speedup vs baseline: 3.1409x; 1.3803x over previous
#include <cuda_runtime.h>
#include <cuda_fp16.h>
#include <cstdint>

// OuterProductMean — fp16 mma.m16n8k16, fused epilogue +
//   (1) mma-based LayerNorm+projection (w converted per-block — no cross-block race)
//   (2) 3-buffer single-barrier phase 2.

#define S_DIM 128
#define R_DIM 256
#define CM    256
#define CC    32
#define CZ    128
#define MDIM  (R_DIM * CC)          // 8192

__device__ __half   g_ah[(size_t)S_DIM * MDIM];    // 2 MB [s][m]
__device__ __half   g_bh[(size_t)S_DIM * MDIM];    // 2 MB [s][n]
__device__ __half   g_wo16[(size_t)CZ * CC * CC];  // 256 KB [z][k2]

// ---------------------------------------------------------------- helpers
__device__ __forceinline__ uint32_t su32(const void* p) {
    uint32_t a;
    asm("{ .reg .u64 t; cvta.to.shared.u64 t, %1; cvt.u32.u64 %0, t; }"
        : "=r"(a) : "l"(p));
    return a;
}
__device__ __forceinline__ void cp16(void* dst_smem, const void* src) {
    asm volatile("cp.async.cg.shared.global [%0], [%1], 16;"
                 :: "r"(su32(dst_smem)), "l"(src));
}
__device__ __forceinline__ void cp_commit() {
    asm volatile("cp.async.commit_group;" ::: "memory");
}
template <int N>
__device__ __forceinline__ void cp_wait() {
    asm volatile("cp.async.wait_group %0;" :: "n"(N) : "memory");
}
__device__ __forceinline__ void mma16(float* d, const uint32_t* a, uint32_t b0, uint32_t b1) {
    asm volatile(
        "mma.sync.aligned.m16n8k16.row.col.f32.f16.f16.f32 "
        "{%0,%1,%2,%3}, {%4,%5,%6,%7}, {%8,%9}, {%0,%1,%2,%3};"
        : "+f"(d[0]), "+f"(d[1]), "+f"(d[2]), "+f"(d[3])
        : "r"(a[0]), "r"(a[1]), "r"(a[2]), "r"(a[3]), "r"(b0), "r"(b1));
}
__device__ __forceinline__ uint32_t h2bits(__half2 h) {
    return *reinterpret_cast<uint32_t*>(&h);
}

// ---------------------------------------------------------------- ln (mma proj)
// blocks 0..255  : (s, 128-row half) LN + mma projection (w converted in-block)
// blocks 256..287: wo -> g_wo16
#define LM_STRIDE 132
#define LM_XS     (64 * LM_STRIDE)                 // 8448  (ws = 64 rows)
#define LM_BS     (LM_XS + 128 * LM_STRIDE)        // 25344 (xs = 128 rows)
#define LM_SMEM   ((LM_BS + 64) * 4)               // 101632 B -> 2 blocks/SM

__global__ __launch_bounds__(256, 2)
void ln_mma_kernel(const float* __restrict__ m,
                   const float* __restrict__ ln_w, const float* __restrict__ ln_b,
                   const float* __restrict__ w1, const float* __restrict__ b1,
                   const float* __restrict__ w2, const float* __restrict__ b2,
                   const float* __restrict__ wo) {
    const int bid = blockIdx.x;
    if (bid >= 2 * S_DIM) {                        // wo -> g_wo16 (32 blocks)
        const int base = ((bid - 2 * S_DIM) * 256 + threadIdx.x) * 16;
        #pragma unroll
        for (int t = 0; t < 4; t++) {
            const float4 v = *(const float4*)&wo[base + 4 * t];
            uint2 u;
            u.x = h2bits(__floats2half2_rn(v.x, v.y));
            u.y = h2bits(__floats2half2_rn(v.z, v.w));
            *(uint2*)&g_wo16[base + 4 * t] = u;
        }
        return;
    }

    extern __shared__ __align__(16) uint32_t smw[];
    uint32_t* ws = smw;                // [64 n][132] fp16 k-paired weights
    uint32_t* xs = smw + LM_XS;        // [128 r][132] LN'd rows fp16 k-paired
    float* bs = (float*)(smw + LM_BS); // [64] biases

    const int s = bid >> 1, half = bid & 1;
    const int tid = threadIdx.x, w = tid >> 5, lane = tid & 31;

    // convert w1/w2 -> ws (fp16 k-paired) directly from global (no race)
    #pragma unroll
    for (int t = 0; t < 32; t++) {
        const int idx = t * 256 + tid;             // 8192 h2 values
        const int n = idx >> 7, q = idx & 127;
        const float* src = (n < 32) ? (w1 + (size_t)n * CM)
                                    : (w2 + (size_t)(n - 32) * CM);
        const float2 v = *(const float2*)&src[2 * q];
        ws[n * LM_STRIDE + q] = h2bits(__floats2half2_rn(v.x, v.y));
    }
    if (tid < 64) bs[tid] = (tid < 32) ? b1[tid] : b2[tid - 32];

    const float4 lw0 = ((const float4*)ln_w)[lane], lw1 = ((const float4*)ln_w)[lane + 32];
    const float4 lb0 = ((const float4*)ln_b)[lane], lb1 = ((const float4*)ln_b)[lane + 32];

    // LN: warp per row, 16 passes
    for (int p = 0; p < 16; p++) {
        const int r = p * 8 + w;
        const float* rowp = m + ((size_t)s * R_DIM + half * 128 + r) * CM;
        const float4 v0 = ((const float4*)rowp)[lane];
        const float4 v1 = ((const float4*)rowp)[lane + 32];
        float sum = v0.x + v0.y + v0.z + v0.w + v1.x + v1.y + v1.z + v1.w;
        #pragma unroll
        for (int o = 16; o; o >>= 1) sum += __shfl_xor_sync(~0u, sum, o);
        const float mu = sum * (1.0f / CM);
        const float d0 = v0.x - mu, d1 = v0.y - mu, d2 = v0.z - mu, d3 = v0.w - mu;
        const float d4 = v1.x - mu, d5 = v1.y - mu, d6 = v1.z - mu, d7 = v1.w - mu;
        float vs = d0*d0 + d1*d1 + d2*d2 + d3*d3 + d4*d4 + d5*d5 + d6*d6 + d7*d7;
        #pragma unroll
        for (int o = 16; o; o >>= 1) vs += __shfl_xor_sync(~0u, vs, o);
        const float rstd = rsqrtf(vs * (1.0f / CM) + 1e-5f);
        uint2 u0, u1;
        u0.x = h2bits(__floats2half2_rn(d0 * rstd * lw0.x + lb0.x, d1 * rstd * lw0.y + lb0.y));
        u0.y = h2bits(__floats2half2_rn(d2 * rstd * lw0.z + lb0.z, d3 * rstd * lw0.w + lb0.w));
        u1.x = h2bits(__floats2half2_rn(d4 * rstd * lw1.x + lb1.x, d5 * rstd * lw1.y + lb1.y));
        u1.y = h2bits(__floats2half2_rn(d6 * rstd * lw1.z + lb1.z, d7 * rstd * lw1.w + lb1.w));
        *(uint2*)&xs[r * LM_STRIDE + 2 * lane]      = u0;
        *(uint2*)&xs[r * LM_STRIDE + 64 + 2 * lane] = u1;
    }
    __syncthreads();

    // mma projection: warp = 16 rows x 64 outs, K=256 (16 k16 steps)
    const int gq = lane >> 2, tg = lane & 3;
    float acc[8][4];
    #pragma unroll
    for (int nt = 0; nt < 8; nt++)
        #pragma unroll
        for (int q = 0; q < 4; q++) acc[nt][q] = 0.f;

    const uint32_t* abase = xs + (16 * w + gq) * LM_STRIDE + tg;
    const uint32_t* bbase = ws + gq * LM_STRIDE + tg;
    #pragma unroll
    for (int ks = 0; ks < 16; ks++) {
        uint32_t a[4];
        const uint32_t* ab = abase + 8 * ks;
        a[0] = ab[0];
        a[1] = ab[8 * LM_STRIDE];
        a[2] = ab[4];
        a[3] = ab[8 * LM_STRIDE + 4];
        #pragma unroll
        for (int nt = 0; nt < 8; nt++) {
            const uint32_t* bb = bbase + nt * 8 * LM_STRIDE + 8 * ks;
            mma16(acc[nt], a, bb[0], bb[4]);
        }
    }

    // epilogue: rows 16w+gq(+8), outs n = 8nt + 2tg (+1)
    const int i_lo = half * 128 + 16 * w + gq;
    #pragma unroll
    for (int nt = 0; nt < 8; nt++) {
        const int n = 8 * nt + 2 * tg;
        const float b0v = bs[n], b1v = bs[n + 1];
        #pragma unroll
        for (int rr = 0; rr < 2; rr++) {
            const int i_abs = i_lo + 8 * rr;
            const __half2 hv = __floats2half2_rn(acc[nt][2 * rr] + b0v,
                                                 acc[nt][2 * rr + 1] + b1v);
            if (n < 32)
                *(__half2*)&g_ah[(size_t)s * MDIM + i_abs * CC + n] = hv;
            else
                *(__half2*)&g_bh[(size_t)s * MDIM + i_abs * CC + (n - 32)] = hv;
        }
    }
}

// ---------------------------------------------------------------- fused
// SMEM (u32/h2 units):
//   sAh [128 m][68] @0 (8704), sBh [256 n][68] @8704 (17408)   phase1
//   Os  [32 p][516] @0 (16512)  (reuses phase1 region)
//   wo bufs 3 x [128 z][68] @26112 (3x8704); reduction scratch reuses them.
#define OPS_STRIDE 68
#define SBH_OFF    8704
#define OS_STRIDE  516
#define WO_OFF     26112
#define WO_BUF     8704
#define FUSED_SMEM ((WO_OFF + 3 * WO_BUF) * 4)    // 208896 B

__device__ __forceinline__ void issue_wo(uint32_t* buf, int cc, int tid) {
    // chunk cc: g_wo16[z][cc*128 .. +127], 128 z rows x 256 B = 2048 cp16
    #pragma unroll
    for (int t = 0; t < 4; t++) {
        const int idx = tid + t * 512;
        const int z = idx >> 4, q = idx & 15;
        cp16(buf + z * OPS_STRIDE + 4 * q,
             g_wo16 + (size_t)z * 1024 + cc * 128 + 8 * q);
    }
}

__global__ __launch_bounds__(512, 1)
void fused_kernel(const float* __restrict__ bo, float* __restrict__ out) {
    extern __shared__ __align__(16) uint32_t smu[];
    const int tid = threadIdx.x, w = tid >> 5, lane = tid & 31;
    const int g = lane >> 2, tg = lane & 3;
    const int i0 = blockIdx.x * 4, j0 = blockIdx.y * 8;
    const int m0 = i0 * CC, n0 = j0 * CC;

    // prefetch wo chunks 0/1 at start (region disjoint from phase-1 operands)
    issue_wo(smu + WO_OFF, 0, tid); cp_commit();
    issue_wo(smu + WO_OFF + WO_BUF, 1, tid); cp_commit();

    // ---- stage + repack: g_ah[s][m] -> sAh[m][k=s] (k-paired half2) ----
    #pragma unroll
    for (int it = 0; it < 4; it++) {
        const int idx = it * 512 + tid;
        const int sp = idx & 63, mq = idx >> 6;
        const uint2 r0 = *(const uint2*)&g_ah[(size_t)(2 * sp) * MDIM + m0 + 4 * mq];
        const uint2 r1 = *(const uint2*)&g_ah[(size_t)(2 * sp + 1) * MDIM + m0 + 4 * mq];
        const __half* h0 = (const __half*)&r0;
        const __half* h1 = (const __half*)&r1;
        #pragma unroll
        for (int t = 0; t < 4; t++)
            smu[(4 * mq + t) * OPS_STRIDE + sp] = h2bits(__halves2half2(h0[t], h1[t]));
    }
    #pragma unroll
    for (int it = 0; it < 8; it++) {
        const int idx = it * 512 + tid;
        const int sp = idx & 63, nq = idx >> 6;
        const uint2 r0 = *(const uint2*)&g_bh[(size_t)(2 * sp) * MDIM + n0 + 4 * nq];
        const uint2 r1 = *(const uint2*)&g_bh[(size_t)(2 * sp + 1) * MDIM + n0 + 4 * nq];
        const __half* h0 = (const __half*)&r0;
        const __half* h1 = (const __half*)&r1;
        #pragma unroll
        for (int t = 0; t < 4; t++)
            smu[SBH_OFF + (4 * nq + t) * OPS_STRIDE + sp] = h2bits(__halves2half2(h0[t], h1[t]));
    }
    __syncthreads();

    // ---- phase 1: o[128][256] = A * B^T over k=128 (8 k16 steps) ----
    const int mr = w >> 2, nc = w & 3;          // warp: 32m x 64n
    float acc[2][8][4];
    #pragma unroll
    for (int mt = 0; mt < 2; mt++)
        #pragma unroll
        for (int nt = 0; nt < 8; nt++)
            #pragma unroll
            for (int q = 0; q < 4; q++) acc[mt][nt][q] = 0.f;

    #pragma unroll
    for (int ks = 0; ks < 8; ks++) {
        uint32_t a[2][4];
        #pragma unroll
        for (int mt = 0; mt < 2; mt++) {
            const uint32_t* base = smu + (32 * mr + 16 * mt + g) * OPS_STRIDE + 8 * ks + tg;
            a[mt][0] = base[0];
            a[mt][1] = base[8 * OPS_STRIDE];
            a[mt][2] = base[4];
            a[mt][3] = base[8 * OPS_STRIDE + 4];
        }
        #pragma unroll
        for (int nt = 0; nt < 8; nt++) {
            const uint32_t* bb = smu + SBH_OFF + (64 * nc + 8 * nt + g) * OPS_STRIDE + 8 * ks + tg;
            const uint32_t b0 = bb[0], b1 = bb[4];
            mma16(acc[0][nt], a[0], b0, b1);
            mma16(acc[1][nt], a[1], b0, b1);
        }
    }
    __syncthreads();   // operands dead; region becomes Os

    // ---- stage o -> Os[p][k2] fp16 (row-major, stride 516 h2) ----
    #pragma unroll
    for (int mt = 0; mt < 2; mt++) {
        #pragma unroll
        for (int nt = 0; nt < 8; nt++) {
            const int p = 8 * mr + 2 * nc + (nt >> 2);
            const int d2 = (4 * nt & 15) + tg;           // (d>>1)
            #pragma unroll
            for (int rr = 0; rr < 2; rr++) {
                const int c = 16 * mt + 8 * rr + g;
                smu[p * OS_STRIDE + c * 16 + d2] =
                    h2bits(__floats2half2_rn(acc[mt][nt][2 * rr], acc[mt][nt][2 * rr + 1]));
            }
        }
    }

    // ---- phase 2: Z[32][128] = Os * wo^T, 8 chunks of 128 k2,
    //      3 buffers, depth-2 prefetch, ONE barrier per chunk ----
    const int kg = w >> 2, zg = w & 3;          // 4 k-groups x 4 z-groups(32 z)
    float zacc[2][4][4];
    #pragma unroll
    for (int mt = 0; mt < 2; mt++)
        #pragma unroll
        for (int nt = 0; nt < 4; nt++)
            #pragma unroll
            for (int q = 0; q < 4; q++) zacc[mt][nt][q] = 0.f;

    for (int cc = 0; cc < 8; cc++) {
        cp_wait<1>();
        __syncthreads();        // chunk cc arrived everywhere; all warps done cc-1
        if (cc + 2 < 8) issue_wo(smu + WO_OFF + ((cc + 2) % 3) * WO_BUF, cc + 2, tid);
        cp_commit();            // unconditional: keeps wait<1> arithmetic valid
        const uint32_t* W = smu + WO_OFF + (cc % 3) * WO_BUF;
        #pragma unroll
        for (int s2 = 0; s2 < 2; s2++) {
            const int kk = 2 * kg + s2;         // k16 step 0..7 within chunk
            const int kb = cc * 64 + kk * 8;    // h2 offset in Os rows
            uint32_t a[2][4];
            #pragma unroll
            for (int mt = 0; mt < 2; mt++) {
                const uint32_t* base = smu + (16 * mt + g) * OS_STRIDE + kb + tg;
                a[mt][0] = base[0];
                a[mt][1] = base[8 * OS_STRIDE];
                a[mt][2] = base[4];
                a[mt][3] = base[8 * OS_STRIDE + 4];
            }
            #pragma unroll
            for (int nt = 0; nt < 4; nt++) {
                const uint32_t* bb = W + (32 * zg + 8 * nt + g) * OPS_STRIDE + kk * 8 + tg;
                const uint32_t b0 = bb[0], b1 = bb[4];
                mma16(zacc[0][nt], a[0], b0, b1);
                mma16(zacc[1][nt], a[1], b0, b1);
            }
        }
    }
    __syncthreads();            // all compute done before scratch reuse

    // ---- 4-way k reduction via SMEM (wo-buf region is dead) ----
    float* zf = &zacc[0][0][0];
    float* scr = (float*)(smu + WO_OFF);        // 2 blocks x 4224 fl
    const int slot = (zg * 32 + lane) * 33;
    if (kg >= 2) {
        float* dst = scr + (kg - 2) * 4224 + slot;
        #pragma unroll
        for (int x = 0; x < 32; x++) dst[x] = zf[x];
    }
    __syncthreads();
    if (kg < 2) {
        const float* src = scr + kg * 4224 + slot;
        #pragma unroll
        for (int x = 0; x < 32; x++) zf[x] += src[x];
    }
    __syncthreads();
    if (kg == 1) {
        float* dst = scr + slot;
        #pragma unroll
        for (int x = 0; x < 32; x++) dst[x] = zf[x];
    }
    __syncthreads();
    if (kg == 0) {
        const float* src = scr + slot;
        #pragma unroll
        for (int x = 0; x < 32; x++) zf[x] += src[x];

        // ---- epilogue ----
        #pragma unroll
        for (int mt = 0; mt < 2; mt++) {
            #pragma unroll
            for (int nt = 0; nt < 4; nt++) {
                const int zz = 32 * zg + 8 * nt + 2 * tg;
                const float2 bo2 = *(const float2*)&bo[zz];
                #pragma unroll
                for (int rr = 0; rr < 2; rr++) {
                    const int p = 16 * mt + 8 * rr + g;
                    const int i = i0 + (p >> 3), j = j0 + (p & 7);
                    float2 v;
                    v.x = (zacc[mt][nt][2 * rr + 0] + bo2.x) * (1.0f / S_DIM);
                    v.y = (zacc[mt][nt][2 * rr + 1] + bo2.y) * (1.0f / S_DIM);
                    *(float2*)&out[((size_t)i * R_DIM + j) * CZ + zz] = v;
                }
            }
        }
    }
}

// ---------------------------------------------------------------- launch
extern "C" void kernel_launch(void* const* d_in, const int* in_sizes, int n_in,
                              void* d_out, int out_size) {
    const float* m    = (const float*)d_in[0];
    const float* ln_w = (const float*)d_in[1];
    const float* ln_b = (const float*)d_in[2];
    const float* w1   = (const float*)d_in[3];
    const float* b1   = (const float*)d_in[4];
    const float* w2   = (const float*)d_in[5];
    const float* b2   = (const float*)d_in[6];
    const float* wo   = (const float*)d_in[7];
    const float* bo   = (const float*)d_in[8];
    float* out = (float*)d_out;

    cudaFuncSetAttribute(ln_mma_kernel, cudaFuncAttributeMaxDynamicSharedMemorySize, LM_SMEM);
    cudaFuncSetAttribute(fused_kernel, cudaFuncAttributeMaxDynamicSharedMemorySize, FUSED_SMEM);

    ln_mma_kernel<<<2 * S_DIM + 32, 256, LM_SMEM>>>(m, ln_w, ln_b, w1, b1, w2, b2, wo);
    fused_kernel<<<dim3(R_DIM / 4, R_DIM / 8), 512, FUSED_SMEM>>>(bo, out);
}